// round 2
// baseline (speedup 1.0000x reference)
#include <cuda_runtime.h>
#include <cuda_bf16.h>
#include <math.h>

// Problem constants
#define B      256
#define NNEG   1000
#define H      3
#define D      128
#define CMAX   250          // neg indices < min(NUM_CLUSTER) = 250
#define CPAD   256          // padded cluster dim
#define EPSF   1e-6f
#define NBLK   148          // one block per SM -> single wave, barrier-safe
#define NT     (32 * 3 * 8) // 768 sim tiles: 32 b-tiles x 3 h x 8 c-tiles

// Device globals (no allocation allowed)
__device__ float g_S[B * H * CPAD];            // sim matrix (dot+1)/2
__device__ float g_loss[B];                    // per-sample loss
__device__ unsigned long long g_bar = 0;       // monotonic grid-barrier ticket

// Monotonic-ticket grid barrier: no resets, replay-safe, deterministic.
__device__ __forceinline__ void grid_barrier() {
    __syncthreads();
    if (threadIdx.x == 0) {
        __threadfence();
        unsigned long long t = atomicAdd(&g_bar, 1ULL);
        unsigned long long target = (t / NBLK + 1ULL) * NBLK;
        while (atomicAdd(&g_bar, 0ULL) < target) { }
        __threadfence();
    }
    __syncthreads();
}

__global__ void __launch_bounds__(256, 1)
hirl_fused(const float* __restrict__ se,
           const float* __restrict__ c0,
           const float* __restrict__ c1,
           const float* __restrict__ c2,
           const int* __restrict__ i2c0,
           const int* __restrict__ i2c1,
           const int* __restrict__ i2c2,
           const int* __restrict__ index,
           const int* __restrict__ neg,
           float* __restrict__ out) {
    // Phase-1 smem
    __shared__ float cn_s[D * 32];      // centroid tile, [d][ci] (16 KB)
    __shared__ float se_s[8 * D];       // se tile, [bi][d]      (4 KB)
    __shared__ float sPart[8 * 32];     // centroid norm partials [seg][ci]
    __shared__ float sInvC[32];
    __shared__ float sInvSe[8];
    // Phase-2 smem
    __shared__ float sS[H * CPAD];
    __shared__ float sPos[H];
    __shared__ int   sLab[H];
    __shared__ float redL[256];
    __shared__ float redC[256];

    const int tid = threadIdx.x;

    // ===================== Phase 1: sim matrix S =====================
    // tile t -> bt = t/24; rem = t%24; h = rem/8; ct = rem%8
    for (int t = blockIdx.x; t < NT; t += NBLK) {
        int bt = t / 24;
        int rem = t - bt * 24;
        int h = rem >> 3, ct = rem & 7;
        int cbase = ct * 32, b0 = bt * 8;
        const float* cents = (h == 0) ? c0 : (h == 1) ? c1 : c2;

        // Load 32 centroid rows (raw), transposed into smem [d][ci].
        for (int i = tid; i < 1024; i += 256) {        // 1024 float4 chunks
            int ci = i & 31, dq = i >> 5;              // dq: which float4 (0..31)
            int c = cbase + ci;
            float4 v = make_float4(0.f, 0.f, 0.f, 0.f);
            if (c < CMAX) v = ((const float4*)(cents + (size_t)c * D))[dq];
            int d = dq * 4;
            cn_s[(d + 0) * 32 + ci] = v.x;
            cn_s[(d + 1) * 32 + ci] = v.y;
            cn_s[(d + 2) * 32 + ci] = v.z;
            cn_s[(d + 3) * 32 + ci] = v.w;
        }
        // Load 8 se rows (raw) [bi][d].
        {
            int bb = tid >> 5, dq = tid & 31;          // 256 = 8 rows x 32 float4
            float4 v = ((const float4*)(se + ((size_t)(b0 + bb) * H + h) * D))[dq];
            int d = dq * 4;
            se_s[bb * D + d + 0] = v.x;
            se_s[bb * D + d + 1] = v.y;
            se_s[bb * D + d + 2] = v.z;
            se_s[bb * D + d + 3] = v.w;
        }
        __syncthreads();

        // Centroid norms: thread (seg, ci) sums 16 d's; then ci<32 folds 8 segs.
        {
            int ci = tid & 31, seg = tid >> 5;
            float ss = 0.0f;
            #pragma unroll
            for (int d = seg * 16; d < seg * 16 + 16; d++) {
                float x = cn_s[d * 32 + ci];
                ss = fmaf(x, x, ss);
            }
            sPart[seg * 32 + ci] = ss;
        }
        // se norms: warp w (<8) reduces row w via float4 + shuffle.
        {
            int w = tid >> 5, lane = tid & 31;
            float4 v = ((const float4*)(se_s + w * D))[lane];
            float s = v.x * v.x + v.y * v.y + v.z * v.z + v.w * v.w;
            #pragma unroll
            for (int o = 16; o > 0; o >>= 1) s += __shfl_xor_sync(0xffffffffu, s, o);
            if (lane == 0) sInvSe[w] = 1.0f / fmaxf(sqrtf(s), 1e-12f);
        }
        __syncthreads();
        if (tid < 32) {
            float ss = 0.0f;
            #pragma unroll
            for (int seg = 0; seg < 8; seg++) ss += sPart[seg * 32 + tid];
            sInvC[tid] = 1.0f / fmaxf(sqrtf(ss), 1e-12f);
        }
        __syncthreads();

        // Compute 8x32 dots.
        {
            int ci = tid & 31, bi = tid >> 5;
            float acc = 0.0f;
            #pragma unroll
            for (int d = 0; d < D; d++)
                acc = fmaf(cn_s[d * 32 + ci], se_s[bi * D + d], acc);
            float sim = acc * sInvC[ci] * sInvSe[bi];
            g_S[((size_t)(b0 + bi) * H + h) * CPAD + cbase + ci] = (sim + 1.0f) * 0.5f;
        }
        __syncthreads();   // protect smem before next tile
    }

    grid_barrier();

    // ===================== Phase 2: per-sample loss =====================
    for (int b = blockIdx.x; b < B; b += NBLK) {
        for (int i = tid; i < H * CPAD; i += 256) sS[i] = g_S[(size_t)b * H * CPAD + i];

        int w = tid >> 5, lane = tid & 31;
        if (w < H) {
            int idx = index[b];
            const int*   i2c   = (w == 0) ? i2c0 : (w == 1) ? i2c1 : i2c2;
            const float* cents = (w == 0) ? c0   : (w == 1) ? c1   : c2;
            int lab = i2c[idx];
            float4 cv = ((const float4*)(cents + (size_t)lab * D))[lane];
            float4 sv = ((const float4*)(se + ((size_t)b * H + w) * D))[lane];
            float cc = cv.x * cv.x + cv.y * cv.y + cv.z * cv.z + cv.w * cv.w;
            float ee = sv.x * sv.x + sv.y * sv.y + sv.z * sv.z + sv.w * sv.w;
            float dd = cv.x * sv.x + cv.y * sv.y + cv.z * sv.z + cv.w * sv.w;
            #pragma unroll
            for (int o = 16; o > 0; o >>= 1) {
                cc += __shfl_xor_sync(0xffffffffu, cc, o);
                ee += __shfl_xor_sync(0xffffffffu, ee, o);
                dd += __shfl_xor_sync(0xffffffffu, dd, o);
            }
            if (lane == 0) {
                float s = dd / (fmaxf(sqrtf(cc), 1e-12f) * fmaxf(sqrtf(ee), 1e-12f));
                sPos[w] = (s + 1.0f) * 0.5f;
                sLab[w] = lab;
            }
        }
        __syncthreads();

        int lab0 = sLab[0], lab1 = sLab[1], lab2 = sLab[2];
        float sumL = 0.0f, cnt = 0.0f;
        for (int n = tid; n < NNEG; n += 256) {
            const int* p = neg + ((size_t)b * NNEG + n) * H;
            int i0 = p[0], i1 = p[1], i2 = p[2];
            float prod = sS[i0] * sS[CPAD + i1] * sS[2 * CPAD + i2];
            bool tn = (i0 != lab0) || (i1 != lab1) || (i2 != lab2);
            if (tn) {
                sumL += -__logf(1.0f - prod + EPSF);
                cnt  += 1.0f;
            }
        }
        redL[tid] = sumL; redC[tid] = cnt;
        __syncthreads();
        #pragma unroll
        for (int s = 128; s > 0; s >>= 1) {
            if (tid < s) { redL[tid] += redL[tid + s]; redC[tid] += redC[tid + s]; }
            __syncthreads();
        }
        if (tid == 0) {
            float posl = -__logf(sPos[0] * sPos[1] * sPos[2] + EPSF);
            float negl = redL[0] / (redC[0] + EPSF);
            g_loss[b] = 0.5f * (posl + negl);
        }
        __syncthreads();
    }

    grid_barrier();

    // ===================== Phase 3: final mean (block 0) =====================
    if (blockIdx.x == 0) {
        redL[tid] = g_loss[tid];
        __syncthreads();
        #pragma unroll
        for (int s = 128; s > 0; s >>= 1) {
            if (tid < s) redL[tid] += redL[tid + s];
            __syncthreads();
        }
        if (tid == 0) out[0] = redL[0] * (1.0f / (float)B);
    }
}

extern "C" void kernel_launch(void* const* d_in, const int* in_sizes, int n_in,
                              void* d_out, int out_size) {
    const float* se  = (const float*)d_in[0];
    const float* c0  = (const float*)d_in[1];
    const float* c1  = (const float*)d_in[2];
    const float* c2  = (const float*)d_in[3];
    const int* i2c0  = (const int*)d_in[4];
    const int* i2c1  = (const int*)d_in[5];
    const int* i2c2  = (const int*)d_in[6];
    const int* index = (const int*)d_in[7];
    const int* neg   = (const int*)d_in[8];
    float* out = (float*)d_out;

    hirl_fused<<<NBLK, 256>>>(se, c0, c1, c2, i2c0, i2c1, i2c2, index, neg, out);
}

// round 3
// speedup vs baseline: 1.4465x; 1.4465x over previous
#include <cuda_runtime.h>
#include <cuda_bf16.h>
#include <math.h>

// Problem constants
#define B      256
#define NNEG   1000
#define H      3
#define D      128
#define CMAX   250          // neg indices < min(NUM_CLUSTER) = 250
#define CPAD   256          // padded cluster dim
#define EPSF   1e-6f

// Device globals (no allocation allowed)
__device__ float g_S[B * H * CPAD];       // sim matrix (dot+1)/2, [b][h][c]
__device__ float g_loss[B];               // per-sample loss
__device__ unsigned int g_done = 0;       // completion counter (reset by last block)

// ---------------------------------------------------------------------------
// K1: fused normalize + sim. One block per (c-tile, b-tile, h).
//     grid = (8 c-tiles of 32, 32 b-tiles of 8, 3 h), block = 256.
//     Norms computed on the fly from raw tiles (validated in R2 phase 1).
// ---------------------------------------------------------------------------
__global__ void k_sim(const float* __restrict__ se,
                      const float* __restrict__ c0,
                      const float* __restrict__ c1,
                      const float* __restrict__ c2) {
    __shared__ float cn_s[D * 32];      // raw centroid tile, [d][ci] (16 KB)
    __shared__ float se_s[8 * D];       // raw se tile, [bi][d]      (4 KB)
    __shared__ float sPart[8 * 32];     // centroid norm partials [seg][ci]
    __shared__ float sInvC[32];
    __shared__ float sInvSe[8];

    const int tid = threadIdx.x;
    const int h = blockIdx.z;
    const int cbase = blockIdx.x * 32;
    const int b0 = blockIdx.y * 8;
    const float* cents = (h == 0) ? c0 : (h == 1) ? c1 : c2;

    // Load 32 centroid rows (raw), transposed into smem [d][ci].
    for (int i = tid; i < 1024; i += 256) {        // 1024 float4 chunks
        int ci = i & 31, dq = i >> 5;
        int c = cbase + ci;
        float4 v = make_float4(0.f, 0.f, 0.f, 0.f);
        if (c < CMAX) v = ((const float4*)(cents + (size_t)c * D))[dq];
        int d = dq * 4;
        cn_s[(d + 0) * 32 + ci] = v.x;
        cn_s[(d + 1) * 32 + ci] = v.y;
        cn_s[(d + 2) * 32 + ci] = v.z;
        cn_s[(d + 3) * 32 + ci] = v.w;
    }
    // Load 8 se rows (raw) [bi][d].
    {
        int bb = tid >> 5, dq = tid & 31;          // 256 = 8 rows x 32 float4
        float4 v = ((const float4*)(se + ((size_t)(b0 + bb) * H + h) * D))[dq];
        int d = dq * 4;
        se_s[bb * D + d + 0] = v.x;
        se_s[bb * D + d + 1] = v.y;
        se_s[bb * D + d + 2] = v.z;
        se_s[bb * D + d + 3] = v.w;
    }
    __syncthreads();

    // Centroid norms: thread (seg, ci) sums 16 d's.
    {
        int ci = tid & 31, seg = tid >> 5;
        float ss = 0.0f;
        #pragma unroll
        for (int d = seg * 16; d < seg * 16 + 16; d++) {
            float x = cn_s[d * 32 + ci];
            ss = fmaf(x, x, ss);
        }
        sPart[seg * 32 + ci] = ss;
    }
    // se norms: warp w (<8) reduces row w.
    {
        int w = tid >> 5, lane = tid & 31;
        float4 v = ((const float4*)(se_s + w * D))[lane];
        float s = v.x * v.x + v.y * v.y + v.z * v.z + v.w * v.w;
        #pragma unroll
        for (int o = 16; o > 0; o >>= 1) s += __shfl_xor_sync(0xffffffffu, s, o);
        if (lane == 0) sInvSe[w] = 1.0f / fmaxf(sqrtf(s), 1e-12f);
    }
    __syncthreads();
    if (tid < 32) {
        float ss = 0.0f;
        #pragma unroll
        for (int seg = 0; seg < 8; seg++) ss += sPart[seg * 32 + tid];
        sInvC[tid] = 1.0f / fmaxf(sqrtf(ss), 1e-12f);
    }
    __syncthreads();

    // 8x32 dots.
    {
        int ci = tid & 31, bi = tid >> 5;
        float acc = 0.0f;
        #pragma unroll
        for (int d = 0; d < D; d++)
            acc = fmaf(cn_s[d * 32 + ci], se_s[bi * D + d], acc);
        float sim = acc * sInvC[ci] * sInvSe[bi];
        g_S[((size_t)(b0 + bi) * H + h) * CPAD + cbase + ci] = (sim + 1.0f) * 0.5f;
    }
}

// ---------------------------------------------------------------------------
// K2: per-sample loss + last-block final mean. One block per b (256 threads).
// ---------------------------------------------------------------------------
__global__ void k_loss(const float* __restrict__ se,
                       const float* __restrict__ c0,
                       const float* __restrict__ c1,
                       const float* __restrict__ c2,
                       const int* __restrict__ i2c0,
                       const int* __restrict__ i2c1,
                       const int* __restrict__ i2c2,
                       const int* __restrict__ index,
                       const int* __restrict__ neg,
                       float* __restrict__ out) {
    __shared__ float sS[H * CPAD];
    __shared__ float sPos[H];
    __shared__ int   sLab[H];
    __shared__ float redL[256];
    __shared__ float redC[256];
    __shared__ int   sLast;

    int b = blockIdx.x, tid = threadIdx.x;
    for (int i = tid; i < H * CPAD; i += 256) sS[i] = g_S[(size_t)b * H * CPAD + i];

    int w = tid >> 5, lane = tid & 31;
    if (w < H) {
        int idx = index[b];
        const int*   i2c   = (w == 0) ? i2c0 : (w == 1) ? i2c1 : i2c2;
        const float* cents = (w == 0) ? c0   : (w == 1) ? c1   : c2;
        int lab = i2c[idx];
        float4 cv = ((const float4*)(cents + (size_t)lab * D))[lane];
        float4 sv = ((const float4*)(se + ((size_t)b * H + w) * D))[lane];
        float cc = cv.x * cv.x + cv.y * cv.y + cv.z * cv.z + cv.w * cv.w;
        float ee = sv.x * sv.x + sv.y * sv.y + sv.z * sv.z + sv.w * sv.w;
        float dd = cv.x * sv.x + cv.y * sv.y + cv.z * sv.z + cv.w * sv.w;
        #pragma unroll
        for (int o = 16; o > 0; o >>= 1) {
            cc += __shfl_xor_sync(0xffffffffu, cc, o);
            ee += __shfl_xor_sync(0xffffffffu, ee, o);
            dd += __shfl_xor_sync(0xffffffffu, dd, o);
        }
        if (lane == 0) {
            float s = dd / (fmaxf(sqrtf(cc), 1e-12f) * fmaxf(sqrtf(ee), 1e-12f));
            sPos[w] = (s + 1.0f) * 0.5f;
            sLab[w] = lab;
        }
    }
    __syncthreads();

    int lab0 = sLab[0], lab1 = sLab[1], lab2 = sLab[2];
    float sumL = 0.0f, cnt = 0.0f;
    for (int n = tid; n < NNEG; n += 256) {
        const int* p = neg + ((size_t)b * NNEG + n) * H;
        int i0 = p[0], i1 = p[1], i2 = p[2];
        float prod = sS[i0] * sS[CPAD + i1] * sS[2 * CPAD + i2];
        bool tn = (i0 != lab0) || (i1 != lab1) || (i2 != lab2);
        if (tn) {
            sumL += -__logf(1.0f - prod + EPSF);
            cnt  += 1.0f;
        }
    }
    redL[tid] = sumL; redC[tid] = cnt;
    __syncthreads();
    #pragma unroll
    for (int s = 128; s > 0; s >>= 1) {
        if (tid < s) { redL[tid] += redL[tid + s]; redC[tid] += redC[tid + s]; }
        __syncthreads();
    }
    if (tid == 0) {
        float posl = -__logf(sPos[0] * sPos[1] * sPos[2] + EPSF);
        float negl = redL[0] / (redC[0] + EPSF);
        g_loss[b] = posl + negl;   // (pos+neg); final mean divides by 2B
        __threadfence();
        unsigned int t = atomicAdd(&g_done, 1u);
        sLast = (t == gridDim.x - 1) ? 1 : 0;
    }
    __syncthreads();

    // Last block deterministically reduces all per-sample losses.
    if (sLast) {
        float v = *((volatile float*)&g_loss[tid]);
        redL[tid] = v;
        __syncthreads();
        #pragma unroll
        for (int s = 128; s > 0; s >>= 1) {
            if (tid < s) redL[tid] += redL[tid + s];
            __syncthreads();
        }
        if (tid == 0) {
            out[0] = redL[0] * (0.5f / (float)B);
            g_done = 0;   // reset for next graph replay (deterministic)
        }
    }
}

// ---------------------------------------------------------------------------
extern "C" void kernel_launch(void* const* d_in, const int* in_sizes, int n_in,
                              void* d_out, int out_size) {
    const float* se  = (const float*)d_in[0];
    const float* c0  = (const float*)d_in[1];
    const float* c1  = (const float*)d_in[2];
    const float* c2  = (const float*)d_in[3];
    const int* i2c0  = (const int*)d_in[4];
    const int* i2c1  = (const int*)d_in[5];
    const int* i2c2  = (const int*)d_in[6];
    const int* index = (const int*)d_in[7];
    const int* neg   = (const int*)d_in[8];
    float* out = (float*)d_out;

    k_sim<<<dim3(CPAD / 32, B / 8, H), 256>>>(se, c0, c1, c2);
    k_loss<<<B, 256>>>(se, c0, c1, c2, i2c0, i2c1, i2c2, index, neg, out);
}

// round 4
// speedup vs baseline: 1.6010x; 1.1068x over previous
#include <cuda_runtime.h>
#include <cuda_bf16.h>
#include <math.h>

// Problem constants
#define B      256
#define NNEG   1000
#define H      3
#define D      128
#define CMAX   250          // neg indices < min(NUM_CLUSTER) = 250
#define CPAD   256          // padded cluster dim
#define EPSF   1e-6f

// Device globals (no allocation allowed)
__device__ float g_S[B * H * CPAD];       // sim matrix (dot+1)/2, [b][h][c]
__device__ float g_posmul[B];             // prod over h of (pos_sim+1)/2
__device__ int   g_lab[B * H];            // positive labels
__device__ float g_loss[B];               // per-sample loss
__device__ unsigned int g_done = 0;       // completion counter (reset by last block)

// ---------------------------------------------------------------------------
// K1: fused normalize + sim + pos-path precompute.
//     grid = (8 c-tiles, 32 b-tiles, 4): z<3 -> sim tiles for hierarchy z,
//     z==3 && x==0 -> pos path for 8 b's (one warp per b).
// ---------------------------------------------------------------------------
__global__ void k_sim(const float* __restrict__ se,
                      const float* __restrict__ c0,
                      const float* __restrict__ c1,
                      const float* __restrict__ c2,
                      const int* __restrict__ i2c0,
                      const int* __restrict__ i2c1,
                      const int* __restrict__ i2c2,
                      const int* __restrict__ index) {
    __shared__ float cn_s[D * 32];      // raw centroid tile, [d][ci] (16 KB)
    __shared__ float se_s[8 * D];       // raw se tile, [bi][d]      (4 KB)
    __shared__ float sPart[8 * 32];     // centroid norm partials [seg][ci]
    __shared__ float sInvC[32];
    __shared__ float sInvSe[8];

    const int tid = threadIdx.x;

    if (blockIdx.z == 3) {
        // ---- pos-path precompute: warp w handles b = b0 + w ----
        if (blockIdx.x != 0) return;
        int w = tid >> 5, lane = tid & 31;
        int b = blockIdx.y * 8 + w;
        int idx = index[b];
        // issue all 3 label loads in parallel
        int lab0 = i2c0[idx], lab1 = i2c1[idx], lab2 = i2c2[idx];
        // issue all centroid/se row loads in parallel
        float4 cv0 = ((const float4*)(c0 + (size_t)lab0 * D))[lane];
        float4 cv1 = ((const float4*)(c1 + (size_t)lab1 * D))[lane];
        float4 cv2 = ((const float4*)(c2 + (size_t)lab2 * D))[lane];
        float4 sv0 = ((const float4*)(se + ((size_t)b * H + 0) * D))[lane];
        float4 sv1 = ((const float4*)(se + ((size_t)b * H + 1) * D))[lane];
        float4 sv2 = ((const float4*)(se + ((size_t)b * H + 2) * D))[lane];

        float prod = 1.0f;
        #pragma unroll
        for (int h = 0; h < H; h++) {
            float4 cv = (h == 0) ? cv0 : (h == 1) ? cv1 : cv2;
            float4 sv = (h == 0) ? sv0 : (h == 1) ? sv1 : sv2;
            float cc = cv.x * cv.x + cv.y * cv.y + cv.z * cv.z + cv.w * cv.w;
            float ee = sv.x * sv.x + sv.y * sv.y + sv.z * sv.z + sv.w * sv.w;
            float dd = cv.x * sv.x + cv.y * sv.y + cv.z * sv.z + cv.w * sv.w;
            #pragma unroll
            for (int o = 16; o > 0; o >>= 1) {
                cc += __shfl_xor_sync(0xffffffffu, cc, o);
                ee += __shfl_xor_sync(0xffffffffu, ee, o);
                dd += __shfl_xor_sync(0xffffffffu, dd, o);
            }
            float s = dd / (fmaxf(sqrtf(cc), 1e-12f) * fmaxf(sqrtf(ee), 1e-12f));
            prod *= (s + 1.0f) * 0.5f;
        }
        if (lane == 0) {
            g_posmul[b] = prod;
            g_lab[b * H + 0] = lab0;
            g_lab[b * H + 1] = lab1;
            g_lab[b * H + 2] = lab2;
        }
        return;
    }

    // ---- sim tile ----
    const int h = blockIdx.z;
    const int cbase = blockIdx.x * 32;
    const int b0 = blockIdx.y * 8;
    const float* cents = (h == 0) ? c0 : (h == 1) ? c1 : c2;

    for (int i = tid; i < 1024; i += 256) {        // 1024 float4 chunks
        int ci = i & 31, dq = i >> 5;
        int c = cbase + ci;
        float4 v = make_float4(0.f, 0.f, 0.f, 0.f);
        if (c < CMAX) v = ((const float4*)(cents + (size_t)c * D))[dq];
        int d = dq * 4;
        cn_s[(d + 0) * 32 + ci] = v.x;
        cn_s[(d + 1) * 32 + ci] = v.y;
        cn_s[(d + 2) * 32 + ci] = v.z;
        cn_s[(d + 3) * 32 + ci] = v.w;
    }
    {
        int bb = tid >> 5, dq = tid & 31;          // 8 rows x 32 float4
        float4 v = ((const float4*)(se + ((size_t)(b0 + bb) * H + h) * D))[dq];
        int d = dq * 4;
        se_s[bb * D + d + 0] = v.x;
        se_s[bb * D + d + 1] = v.y;
        se_s[bb * D + d + 2] = v.z;
        se_s[bb * D + d + 3] = v.w;
    }
    __syncthreads();

    {
        int ci = tid & 31, seg = tid >> 5;
        float ss = 0.0f;
        #pragma unroll
        for (int d = seg * 16; d < seg * 16 + 16; d++) {
            float x = cn_s[d * 32 + ci];
            ss = fmaf(x, x, ss);
        }
        sPart[seg * 32 + ci] = ss;
    }
    {
        int w = tid >> 5, lane = tid & 31;
        float4 v = ((const float4*)(se_s + w * D))[lane];
        float s = v.x * v.x + v.y * v.y + v.z * v.z + v.w * v.w;
        #pragma unroll
        for (int o = 16; o > 0; o >>= 1) s += __shfl_xor_sync(0xffffffffu, s, o);
        if (lane == 0) sInvSe[w] = 1.0f / fmaxf(sqrtf(s), 1e-12f);
    }
    __syncthreads();
    if (tid < 32) {
        float ss = 0.0f;
        #pragma unroll
        for (int seg = 0; seg < 8; seg++) ss += sPart[seg * 32 + tid];
        sInvC[tid] = 1.0f / fmaxf(sqrtf(ss), 1e-12f);
    }
    __syncthreads();

    {
        int ci = tid & 31, bi = tid >> 5;
        float acc = 0.0f;
        #pragma unroll
        for (int d = 0; d < D; d++)
            acc = fmaf(cn_s[d * 32 + ci], se_s[bi * D + d], acc);
        float sim = acc * sInvC[ci] * sInvSe[bi];
        g_S[((size_t)(b0 + bi) * H + h) * CPAD + cbase + ci] = (sim + 1.0f) * 0.5f;
    }
}

// ---------------------------------------------------------------------------
// K2: one thread per negative. Block = 1024 threads, one block per b.
//     Direct L1/L2 lookups into g_S (no smem staging). Shuffle reductions.
//     Last block computes the final mean.
// ---------------------------------------------------------------------------
__global__ void __launch_bounds__(1024)
k_loss(const int* __restrict__ neg, float* __restrict__ out) {
    __shared__ float rL[32];
    __shared__ float rC[32];
    __shared__ int   sLast;

    const int b = blockIdx.x, tid = threadIdx.x;
    const int w = tid >> 5, lane = tid & 31;

    // broadcast labels (L1/const-cached)
    const int lab0 = g_lab[b * H + 0];
    const int lab1 = g_lab[b * H + 1];
    const int lab2 = g_lab[b * H + 2];

    float sumL = 0.0f, cnt = 0.0f;
    if (tid < NNEG) {
        const int* p = neg + ((size_t)b * NNEG + tid) * H;
        int i0 = p[0], i1 = p[1], i2 = p[2];
        float s0 = g_S[((size_t)b * H + 0) * CPAD + i0];
        float s1 = g_S[((size_t)b * H + 1) * CPAD + i1];
        float s2 = g_S[((size_t)b * H + 2) * CPAD + i2];
        float prod = s0 * s1 * s2;
        bool tn = (i0 != lab0) || (i1 != lab1) || (i2 != lab2);
        if (tn) {
            sumL = -__logf(1.0f - prod + EPSF);
            cnt  = 1.0f;
        }
    }
    #pragma unroll
    for (int o = 16; o > 0; o >>= 1) {
        sumL += __shfl_xor_sync(0xffffffffu, sumL, o);
        cnt  += __shfl_xor_sync(0xffffffffu, cnt,  o);
    }
    if (lane == 0) { rL[w] = sumL; rC[w] = cnt; }
    __syncthreads();
    if (tid < 32) {
        float sL = rL[tid], sC = rC[tid];
        #pragma unroll
        for (int o = 16; o > 0; o >>= 1) {
            sL += __shfl_xor_sync(0xffffffffu, sL, o);
            sC += __shfl_xor_sync(0xffffffffu, sC, o);
        }
        if (tid == 0) {
            float negl = sL / (sC + EPSF);
            float posl = -__logf(g_posmul[b] + EPSF);
            g_loss[b] = 0.5f * (posl + negl);
            __threadfence();
            unsigned int t = atomicAdd(&g_done, 1u);
            sLast = (t == gridDim.x - 1) ? 1 : 0;
        }
    }
    __syncthreads();

    // Last block: deterministic final mean over B=256 per-sample losses.
    if (sLast) {
        __threadfence();
        float v = 0.0f;
        if (tid < B) v = *((volatile float*)&g_loss[tid]);
        if (tid < 256) {
            #pragma unroll
            for (int o = 16; o > 0; o >>= 1) v += __shfl_xor_sync(0xffffffffu, v, o);
            if (lane == 0) rL[w] = v;   // w in 0..7
        }
        __syncthreads();
        if (tid == 0) {
            float total = 0.0f;
            #pragma unroll
            for (int i = 0; i < 8; i++) total += rL[i];
            out[0] = total * (1.0f / (float)B);
            g_done = 0;   // reset for next graph replay
        }
    }
}

// ---------------------------------------------------------------------------
extern "C" void kernel_launch(void* const* d_in, const int* in_sizes, int n_in,
                              void* d_out, int out_size) {
    const float* se  = (const float*)d_in[0];
    const float* c0  = (const float*)d_in[1];
    const float* c1  = (const float*)d_in[2];
    const float* c2  = (const float*)d_in[3];
    const int* i2c0  = (const int*)d_in[4];
    const int* i2c1  = (const int*)d_in[5];
    const int* i2c2  = (const int*)d_in[6];
    const int* index = (const int*)d_in[7];
    const int* neg   = (const int*)d_in[8];
    float* out = (float*)d_out;

    k_sim<<<dim3(8, 32, 4), 256>>>(se, c0, c1, c2, i2c0, i2c1, i2c2, index);
    k_loss<<<B, 1024>>>(neg, out);
}

// round 5
// speedup vs baseline: 1.6199x; 1.0118x over previous
#include <cuda_runtime.h>
#include <cuda_bf16.h>
#include <math.h>

// Problem constants
#define B      256
#define NNEG   1000
#define H      3
#define D      128
#define CMAX   250          // neg indices < min(NUM_CLUSTER) = 250
#define CPAD   256          // padded cluster dim
#define EPSF   1e-6f
#define CT     64           // c-tile width
#define BT     16           // b-tile height
#define NEG_F4 ((B * NNEG * H) / 4)   // 192000 float4 elements in neg

// Device globals (no allocation allowed)
__device__ float g_S[B * H * CPAD];       // sim matrix (dot+1)/2, [b][h][c]
__device__ float g_posmul[B];             // prod over h of (pos_sim+1)/2
__device__ int   g_lab[B * H];            // positive labels
__device__ float g_loss[B];               // per-sample loss
__device__ unsigned int g_done = 0;       // completion counter

// ---------------------------------------------------------------------------
// K1: fused normalize + sim (register-tiled) + pos-path + neg L2-prefetch.
//     grid = (4, 16, 4), block = 256.
//       z<3           : sim tile (c-tile x, b-tile y, hierarchy z)
//       z==3          : block id = y*4+x (0..63):
//                         warps 0-3: pos path for b = id*4 + w
//                         warps 4-7: prefetch neg slice into L2
// ---------------------------------------------------------------------------
__global__ void k_sim(const float* __restrict__ se,
                      const float* __restrict__ c0,
                      const float* __restrict__ c1,
                      const float* __restrict__ c2,
                      const int* __restrict__ i2c0,
                      const int* __restrict__ i2c1,
                      const int* __restrict__ i2c2,
                      const int* __restrict__ index,
                      const int* __restrict__ neg) {
    __shared__ float cn_s[D * CT];      // raw centroid tile, [d][c] (32 KB)
    __shared__ float se_s[BT * D];      // raw se tile, [bi][d]      (8 KB)
    __shared__ float sPart[4 * CT];     // centroid norm partials [seg][c]
    __shared__ float sInvC[CT];
    __shared__ float sInvSe[BT];

    const int tid = threadIdx.x;

    if (blockIdx.z == 3) {
        int id = blockIdx.y * 4 + blockIdx.x;   // 0..63
        int w = tid >> 5, lane = tid & 31;
        if (w < 4) {
            // ---- pos path: b = id*4 + w ----
            int b = id * 4 + w;
            int idx = index[b];
            int lab0 = i2c0[idx], lab1 = i2c1[idx], lab2 = i2c2[idx];
            float4 cv0 = ((const float4*)(c0 + (size_t)lab0 * D))[lane];
            float4 cv1 = ((const float4*)(c1 + (size_t)lab1 * D))[lane];
            float4 cv2 = ((const float4*)(c2 + (size_t)lab2 * D))[lane];
            float4 sv0 = ((const float4*)(se + ((size_t)b * H + 0) * D))[lane];
            float4 sv1 = ((const float4*)(se + ((size_t)b * H + 1) * D))[lane];
            float4 sv2 = ((const float4*)(se + ((size_t)b * H + 2) * D))[lane];

            float prod = 1.0f;
            #pragma unroll
            for (int h = 0; h < H; h++) {
                float4 cv = (h == 0) ? cv0 : (h == 1) ? cv1 : cv2;
                float4 sv = (h == 0) ? sv0 : (h == 1) ? sv1 : sv2;
                float cc = cv.x * cv.x + cv.y * cv.y + cv.z * cv.z + cv.w * cv.w;
                float ee = sv.x * sv.x + sv.y * sv.y + sv.z * sv.z + sv.w * sv.w;
                float dd = cv.x * sv.x + cv.y * sv.y + cv.z * sv.z + cv.w * sv.w;
                #pragma unroll
                for (int o = 16; o > 0; o >>= 1) {
                    cc += __shfl_xor_sync(0xffffffffu, cc, o);
                    ee += __shfl_xor_sync(0xffffffffu, ee, o);
                    dd += __shfl_xor_sync(0xffffffffu, dd, o);
                }
                float s = dd / (fmaxf(sqrtf(cc), 1e-12f) * fmaxf(sqrtf(ee), 1e-12f));
                prod *= (s + 1.0f) * 0.5f;
            }
            if (lane == 0) {
                g_posmul[b] = prod;
                g_lab[b * H + 0] = lab0;
                g_lab[b * H + 1] = lab1;
                g_lab[b * H + 2] = lab2;
            }
        } else {
            // ---- neg prefetch into L2: 8192 threads stride over 192000 f4 ----
            int local = tid - 128;                 // 0..127
            int gid = id * 128 + local;            // 0..8191
            const float4* np = (const float4*)neg;
            for (int i = gid; i < NEG_F4; i += 64 * 128) {
                unsigned ra, rb, rc, rd;
                asm volatile("ld.global.cg.v4.u32 {%0,%1,%2,%3}, [%4];"
                             : "=r"(ra), "=r"(rb), "=r"(rc), "=r"(rd)
                             : "l"(np + i));
            }
        }
        return;
    }

    // ---- sim tile: BT=16 b's x CT=64 c's, 4 outputs per thread ----
    const int h = blockIdx.z;
    const int cbase = blockIdx.x * CT;
    const int b0 = blockIdx.y * BT;
    const float* cents = (h == 0) ? c0 : (h == 1) ? c1 : c2;

    // Load 64 centroid rows (raw), transposed into cn_s[d][c].
    for (int i = tid; i < CT * 32; i += 256) {     // 2048 float4 chunks
        int c = i & (CT - 1), dq = i >> 6;         // dq: float4 index 0..31
        int cg = cbase + c;
        float4 v = make_float4(0.f, 0.f, 0.f, 0.f);
        if (cg < CMAX) v = ((const float4*)(cents + (size_t)cg * D))[dq];
        int d = dq * 4;
        cn_s[(d + 0) * CT + c] = v.x;
        cn_s[(d + 1) * CT + c] = v.y;
        cn_s[(d + 2) * CT + c] = v.z;
        cn_s[(d + 3) * CT + c] = v.w;
    }
    // Load 16 se rows (raw) [bi][d].
    for (int i = tid; i < BT * 32; i += 256) {     // 512 float4 chunks
        int bb = i >> 5, dq = i & 31;
        float4 v = ((const float4*)(se + ((size_t)(b0 + bb) * H + h) * D))[dq];
        int d = dq * 4;
        se_s[bb * D + d + 0] = v.x;
        se_s[bb * D + d + 1] = v.y;
        se_s[bb * D + d + 2] = v.z;
        se_s[bb * D + d + 3] = v.w;
    }
    __syncthreads();

    // Centroid norm partials: seg = tid>>6 (0..3) sums 32 d's for c = tid&63.
    {
        int c = tid & (CT - 1), seg = tid >> 6;
        float ss = 0.0f;
        #pragma unroll
        for (int d = seg * 32; d < seg * 32 + 32; d++) {
            float x = cn_s[d * CT + c];
            ss = fmaf(x, x, ss);
        }
        sPart[seg * CT + c] = ss;
    }
    // se norms: warp w handles rows 2w, 2w+1.
    {
        int w = tid >> 5, lane = tid & 31;
        #pragma unroll
        for (int r = 0; r < 2; r++) {
            int row = w * 2 + r;
            float4 v = ((const float4*)(se_s + row * D))[lane];
            float s = v.x * v.x + v.y * v.y + v.z * v.z + v.w * v.w;
            #pragma unroll
            for (int o = 16; o > 0; o >>= 1) s += __shfl_xor_sync(0xffffffffu, s, o);
            if (lane == 0) sInvSe[row] = 1.0f / fmaxf(sqrtf(s), 1e-12f);
        }
    }
    __syncthreads();
    if (tid < CT) {
        float ss = sPart[tid] + sPart[CT + tid] + sPart[2 * CT + tid] + sPart[3 * CT + tid];
        sInvC[tid] = 1.0f / fmaxf(sqrtf(ss), 1e-12f);
    }
    __syncthreads();

    // Main loop: thread (bi = tid>>4, ci = tid&15) computes c = ci*4 .. +3.
    {
        int bi = tid >> 4, ci = tid & 15;
        int cq = ci * 4;
        float a0 = 0.f, a1 = 0.f, a2 = 0.f, a3 = 0.f;
        const float* ses = se_s + bi * D;
        #pragma unroll 8
        for (int d = 0; d < D; d++) {
            float sv = ses[d];
            float4 cv = *((const float4*)(cn_s + d * CT + cq));
            a0 = fmaf(sv, cv.x, a0);
            a1 = fmaf(sv, cv.y, a1);
            a2 = fmaf(sv, cv.z, a2);
            a3 = fmaf(sv, cv.w, a3);
        }
        float invse = sInvSe[bi];
        float4 r;
        r.x = (a0 * sInvC[cq + 0] * invse + 1.0f) * 0.5f;
        r.y = (a1 * sInvC[cq + 1] * invse + 1.0f) * 0.5f;
        r.z = (a2 * sInvC[cq + 2] * invse + 1.0f) * 0.5f;
        r.w = (a3 * sInvC[cq + 3] * invse + 1.0f) * 0.5f;
        *((float4*)(g_S + ((size_t)(b0 + bi) * H + h) * CPAD + cbase + cq)) = r;
    }
}

// ---------------------------------------------------------------------------
// K2: one thread per negative. Block = 1024 threads, one block per b.
//     cnt via ballot/popc; sumL via shuffle. Last block does final mean.
// ---------------------------------------------------------------------------
__global__ void __launch_bounds__(1024)
k_loss(const int* __restrict__ neg, float* __restrict__ out) {
    __shared__ float rL[32];
    __shared__ int   rC[32];
    __shared__ int   sLast;

    const int b = blockIdx.x, tid = threadIdx.x;
    const int w = tid >> 5, lane = tid & 31;

    const int lab0 = g_lab[b * H + 0];
    const int lab1 = g_lab[b * H + 1];
    const int lab2 = g_lab[b * H + 2];

    float sumL = 0.0f;
    bool tn = false;
    if (tid < NNEG) {
        const int* p = neg + ((size_t)b * NNEG + tid) * H;
        int i0 = p[0], i1 = p[1], i2 = p[2];
        float s0 = g_S[((size_t)b * H + 0) * CPAD + i0];
        float s1 = g_S[((size_t)b * H + 1) * CPAD + i1];
        float s2 = g_S[((size_t)b * H + 2) * CPAD + i2];
        float prod = s0 * s1 * s2;
        tn = (i0 != lab0) || (i1 != lab1) || (i2 != lab2);
        if (tn) sumL = -__logf(1.0f - prod + EPSF);
    }
    unsigned bm = __ballot_sync(0xffffffffu, tn);
    #pragma unroll
    for (int o = 16; o > 0; o >>= 1)
        sumL += __shfl_xor_sync(0xffffffffu, sumL, o);
    if (lane == 0) { rL[w] = sumL; rC[w] = __popc(bm); }
    __syncthreads();
    if (tid < 32) {
        float sL = rL[tid];
        float sC = (float)rC[tid];
        #pragma unroll
        for (int o = 16; o > 0; o >>= 1) {
            sL += __shfl_xor_sync(0xffffffffu, sL, o);
            sC += __shfl_xor_sync(0xffffffffu, sC, o);
        }
        if (tid == 0) {
            float negl = sL / (sC + EPSF);
            float posl = -__logf(g_posmul[b] + EPSF);
            g_loss[b] = 0.5f * (posl + negl);
            __threadfence();
            unsigned int t = atomicAdd(&g_done, 1u);
            sLast = (t == gridDim.x - 1) ? 1 : 0;
        }
    }
    __syncthreads();

    if (sLast) {
        __threadfence();
        float v = 0.0f;
        if (tid < B) v = *((volatile float*)&g_loss[tid]);
        if (tid < 256) {
            #pragma unroll
            for (int o = 16; o > 0; o >>= 1) v += __shfl_xor_sync(0xffffffffu, v, o);
            if (lane == 0) rL[w] = v;   // w in 0..7
        }
        __syncthreads();
        if (tid == 0) {
            float total = 0.0f;
            #pragma unroll
            for (int i = 0; i < 8; i++) total += rL[i];
            out[0] = total * (1.0f / (float)B);
            g_done = 0;   // reset for next graph replay
        }
    }
}

// ---------------------------------------------------------------------------
extern "C" void kernel_launch(void* const* d_in, const int* in_sizes, int n_in,
                              void* d_out, int out_size) {
    const float* se  = (const float*)d_in[0];
    const float* c0  = (const float*)d_in[1];
    const float* c1  = (const float*)d_in[2];
    const float* c2  = (const float*)d_in[3];
    const int* i2c0  = (const int*)d_in[4];
    const int* i2c1  = (const int*)d_in[5];
    const int* i2c2  = (const int*)d_in[6];
    const int* index = (const int*)d_in[7];
    const int* neg   = (const int*)d_in[8];
    float* out = (float*)d_out;

    k_sim<<<dim3(4, 16, 4), 256>>>(se, c0, c1, c2, i2c0, i2c1, i2c2, index, neg);
    k_loss<<<B, 1024>>>(neg, out);
}